// round 1
// baseline (speedup 1.0000x reference)
#include <cuda_runtime.h>
#include <math.h>

// Problem constants (fixed by the reference setup_inputs)
#define BB 16
#define SS 8
#define CC 3
#define KK 6
#define HH 128
#define WW 128
#define HW (HH*WW)          // 16384
#define CHUNK 512
#define NCHUNK (HW/CHUNK)   // 32
#define NTHREADS 288        // 9 warps
#define EPSF 1.1920928955078125e-07f

// slots per chunk in the moment-partial buffer:
//   8 warps * 72 first-moment entries (s,k,a(3),b(4)) = 576
//   6*10 symmetric second-moment entries             = 60
//   6 gp sums                                         = 6
#define NSLOT 642

// ---------------- device scratch (no allocations allowed) ----------------
__device__ float g_gp[BB*KK*HW];            // softmax probs per pixel
__device__ float g_part[BB*NCHUNK*NSLOT];   // per-chunk moment partials
__device__ float g_first[BB*SS*KK*12];      // reduced first moments (raw)
__device__ float g_sec[BB*KK*10];           // reduced second moments (sym4)
__device__ float g_pn[BB*KK];               // 1/sum(gp)
__device__ float g_ops[BB*SS*KK*12];        // ops[u,s,k,a(3),b(4)]
__device__ float g_partC[BB*NCHUNK*SS*KK*6];// per-chunk sigma partials (sym3)
__device__ float g_siginv[BB*SS*KK*6];      // sigma^-1 (sym3)
__device__ float g_ldsum[BB*KK];            // sum_s logdet(sigma)

// ---------------- fused accumulate kernel ----------------
// MODE 0: initial pass (generated=0): softmax(pred) -> gp, accumulate moments
// MODE 1: E-step + next M-step accumulate: quad -> generated -> softmax -> gp -> moments
// MODE 2: final E-step: quad -> generated -> write output
template<int MODE>
__global__ __launch_bounds__(NTHREADS)
void accum_kernel(const float* __restrict__ img, const float* __restrict__ shifted,
                  const float* __restrict__ pred, float* __restrict__ out)
{
    __shared__ float s_gp[KK*CHUNK];   // 12 KB
    __shared__ float s_img[CC*CHUNK];  // 6 KB
    __shared__ float s_ops[SS*KK*12];  // 2.25 KB
    __shared__ float s_sinv[SS*KK*6];  // 1.125 KB
    __shared__ float s_ld[KK];

    const int u    = blockIdx.y;
    const int base = blockIdx.x * CHUNK;
    const int tid  = threadIdx.x;

    if (MODE >= 1) {
        for (int i = tid; i < SS*KK*12; i += NTHREADS) s_ops[i]  = g_ops[u*SS*KK*12 + i];
        for (int i = tid; i < SS*KK*6;  i += NTHREADS) s_sinv[i] = g_siginv[u*SS*KK*6 + i];
        if (tid < KK) s_ld[tid] = g_ldsum[u*KK + tid];
        __syncthreads();
    }

    const float* imgU  = img  + (size_t)u*CC*HW;
    const float* shU   = shifted + (size_t)u*SS*CC*HW;
    const float* predU = pred + (size_t)u*KK*HW;
    float* gpU = g_gp + (size_t)u*KK*HW;

    // ---- phase 1: per-pixel quad / generated / softmax ----
    for (int p = tid; p < CHUNK; p += NTHREADS) {
        const int pix = base + p;
        const float pb0 = imgU[0*HW + pix];
        const float pb1 = imgU[1*HW + pix];
        const float pb2 = imgU[2*HW + pix];
        s_img[0*CHUNK + p] = pb0;
        s_img[1*CHUNK + p] = pb1;
        s_img[2*CHUNK + p] = pb2;

        float gen[KK];
        if (MODE >= 1) {
            float quad[KK];
            #pragma unroll
            for (int k = 0; k < KK; k++) quad[k] = 0.f;
            #pragma unroll
            for (int s = 0; s < SS; s++) {
                const float x0 = shU[(s*CC+0)*HW + pix];
                const float x1 = shU[(s*CC+1)*HW + pix];
                const float x2 = shU[(s*CC+2)*HW + pix];
                #pragma unroll
                for (int k = 0; k < KK; k++) {
                    const float* O = s_ops + (s*KK+k)*12;
                    const float d0 = x0 - (O[0]*pb0 + O[1]*pb1 + O[2]*pb2  + O[3]);
                    const float d1 = x1 - (O[4]*pb0 + O[5]*pb1 + O[6]*pb2  + O[7]);
                    const float d2 = x2 - (O[8]*pb0 + O[9]*pb1 + O[10]*pb2 + O[11]);
                    const float* Si = s_sinv + (s*KK+k)*6;
                    quad[k] += Si[0]*d0*d0 + Si[3]*d1*d1 + Si[5]*d2*d2
                             + 2.f*(Si[1]*d0*d1 + Si[2]*d0*d2 + Si[4]*d1*d2);
                }
            }
            #pragma unroll
            for (int k = 0; k < KK; k++) gen[k] = -0.5f*quad[k] - 0.5f*s_ld[k];
        } else {
            #pragma unroll
            for (int k = 0; k < KK; k++) gen[k] = 0.f;
        }

        if (MODE == 2) {
            #pragma unroll
            for (int k = 0; k < KK; k++) out[((size_t)u*KK + k)*HW + pix] = gen[k];
        } else {
            float lg[KK];
            float mx = -1e30f;
            #pragma unroll
            for (int k = 0; k < KK; k++) {
                lg[k] = predU[k*HW + pix] + gen[k];
                mx = fmaxf(mx, lg[k]);
            }
            float sum = 0.f;
            #pragma unroll
            for (int k = 0; k < KK; k++) { lg[k] = expf(lg[k] - mx); sum += lg[k]; }
            const float inv = 1.f / sum;
            #pragma unroll
            for (int k = 0; k < KK; k++) {
                const float g = lg[k]*inv + EPSF;
                s_gp[k*CHUNK + p] = g;
                gpU[k*HW + pix] = g;
            }
        }
    }
    if (MODE == 2) return;
    __syncthreads();

    // ---- phase 2: moment accumulation (warp-specialized) ----
    const int warp = tid >> 5, lane = tid & 31;
    float* part = g_part + (size_t)(u*NCHUNK + blockIdx.x)*NSLOT;

    if (warp < SS) {
        const int s = warp;
        float acc[72];
        #pragma unroll
        for (int j = 0; j < 72; j++) acc[j] = 0.f;
        for (int i = 0; i < CHUNK/32; i++) {
            const int p = lane + 32*i;
            const int pix = base + p;
            const float x0 = shU[(s*CC+0)*HW + pix];
            const float x1 = shU[(s*CC+1)*HW + pix];
            const float x2 = shU[(s*CC+2)*HW + pix];
            const float pb0 = s_img[p], pb1 = s_img[CHUNK+p], pb2 = s_img[2*CHUNK+p];
            #pragma unroll
            for (int k = 0; k < KK; k++) {
                const float wk = s_gp[k*CHUNK + p];
                const float t0 = x0*wk, t1 = x1*wk, t2 = x2*wk;
                acc[k*12+0]  += t0*pb0; acc[k*12+1]  += t0*pb1; acc[k*12+2]  += t0*pb2; acc[k*12+3]  += t0;
                acc[k*12+4]  += t1*pb0; acc[k*12+5]  += t1*pb1; acc[k*12+6]  += t1*pb2; acc[k*12+7]  += t1;
                acc[k*12+8]  += t2*pb0; acc[k*12+9]  += t2*pb1; acc[k*12+10] += t2*pb2; acc[k*12+11] += t2;
            }
        }
        #pragma unroll
        for (int j = 0; j < 72; j++) {
            float v = acc[j];
            #pragma unroll
            for (int off = 16; off > 0; off >>= 1) v += __shfl_down_sync(0xffffffffu, v, off);
            if (lane == 0) part[s*72 + j] = v;
        }
    } else {
        // warp 8: symmetric second moments of padded (sym4, 10 entries) + gp sums
        float acc[60], gs[KK];
        #pragma unroll
        for (int j = 0; j < 60; j++) acc[j] = 0.f;
        #pragma unroll
        for (int k = 0; k < KK; k++) gs[k] = 0.f;
        for (int i = 0; i < CHUNK/32; i++) {
            const int p = lane + 32*i;
            const float pb0 = s_img[p], pb1 = s_img[CHUNK+p], pb2 = s_img[2*CHUNK+p];
            const float q0 = pb0*pb0, q1 = pb0*pb1, q2 = pb0*pb2, q3 = pb0;
            const float q4 = pb1*pb1, q5 = pb1*pb2, q6 = pb1;
            const float q7 = pb2*pb2, q8 = pb2;
            #pragma unroll
            for (int k = 0; k < KK; k++) {
                const float wk = s_gp[k*CHUNK + p];
                gs[k] += wk;
                acc[k*10+0] += wk*q0; acc[k*10+1] += wk*q1; acc[k*10+2] += wk*q2; acc[k*10+3] += wk*q3;
                acc[k*10+4] += wk*q4; acc[k*10+5] += wk*q5; acc[k*10+6] += wk*q6;
                acc[k*10+7] += wk*q7; acc[k*10+8] += wk*q8; acc[k*10+9] += wk;
            }
        }
        #pragma unroll
        for (int j = 0; j < 60; j++) {
            float v = acc[j];
            #pragma unroll
            for (int off = 16; off > 0; off >>= 1) v += __shfl_down_sync(0xffffffffu, v, off);
            if (lane == 0) part[576 + j] = v;
        }
        #pragma unroll
        for (int k = 0; k < KK; k++) {
            float v = gs[k];
            #pragma unroll
            for (int off = 16; off > 0; off >>= 1) v += __shfl_down_sync(0xffffffffu, v, off);
            if (lane == 0) part[636 + k] = v;
        }
    }
}

// ---------------- deterministic fixed-order partial reduction ----------------
__global__ void reduceA_kernel()
{
    const int u = blockIdx.x;
    const int slot = threadIdx.x;   // block of NSLOT threads
    float v = 0.f;
    const float* p = g_part + (size_t)u*NCHUNK*NSLOT + slot;
    for (int c = 0; c < NCHUNK; c++) v += p[c*NSLOT];
    if (slot < 576)      g_first[u*576 + slot] = v;
    else if (slot < 636) g_sec[u*60 + (slot - 576)] = v;
    else                 g_pn[u*KK + (slot - 636)] = 1.f / v;
}

// ---------------- tiny per-(u,k) 4x4 solve -> ops ----------------
__global__ void ops_kernel()
{
    const int t = threadIdx.x;
    if (t >= BB*KK) return;
    const int u = t / KK, k = t % KK;

    const float* sec = g_sec + (u*KK + k)*10;
    const float trace = sec[0] + sec[4] + sec[7] + sec[9];
    const float norm = 1.f / trace;

    float M[4][4], Inv[4][4];
    M[0][0]=sec[0]; M[0][1]=sec[1]; M[0][2]=sec[2]; M[0][3]=sec[3];
    M[1][0]=sec[1]; M[1][1]=sec[4]; M[1][2]=sec[5]; M[1][3]=sec[6];
    M[2][0]=sec[2]; M[2][1]=sec[5]; M[2][2]=sec[7]; M[2][3]=sec[8];
    M[3][0]=sec[3]; M[3][1]=sec[6]; M[3][2]=sec[8]; M[3][3]=sec[9];
    for (int i = 0; i < 4; i++) {
        for (int j = 0; j < 4; j++) { M[i][j] *= norm; Inv[i][j] = (i==j) ? 1.f : 0.f; }
        M[i][i] += EPSF;
    }
    // Gauss-Jordan with partial pivoting
    for (int col = 0; col < 4; col++) {
        int piv = col; float best = fabsf(M[col][col]);
        for (int r = col+1; r < 4; r++) {
            const float v = fabsf(M[r][col]);
            if (v > best) { best = v; piv = r; }
        }
        if (piv != col) {
            for (int j = 0; j < 4; j++) {
                float tmp = M[col][j]; M[col][j] = M[piv][j]; M[piv][j] = tmp;
                tmp = Inv[col][j]; Inv[col][j] = Inv[piv][j]; Inv[piv][j] = tmp;
            }
        }
        const float d = 1.f / M[col][col];
        for (int j = 0; j < 4; j++) { M[col][j] *= d; Inv[col][j] *= d; }
        for (int r = 0; r < 4; r++) {
            if (r == col) continue;
            const float f = M[r][col];
            for (int j = 0; j < 4; j++) { M[r][j] -= f*M[col][j]; Inv[r][j] -= f*Inv[col][j]; }
        }
    }
    for (int s = 0; s < SS; s++) {
        const float* F = g_first + u*576 + s*72 + k*12;
        float* O = g_ops + u*576 + s*72 + k*12;
        for (int a = 0; a < 3; a++) {
            const float f0 = F[a*4+0]*norm, f1 = F[a*4+1]*norm, f2 = F[a*4+2]*norm, f3 = F[a*4+3]*norm;
            for (int c = 0; c < 4; c++)
                O[a*4+c] = f0*Inv[0][c] + f1*Inv[1][c] + f2*Inv[2][c] + f3*Inv[3][c];
        }
    }
}

// ---------------- sigma accumulation ----------------
__global__ __launch_bounds__(NTHREADS)
void sigacc_kernel(const float* __restrict__ img, const float* __restrict__ shifted)
{
    __shared__ float s_gp[KK*CHUNK];
    __shared__ float s_img[CC*CHUNK];
    __shared__ float s_ops[SS*KK*12];
    __shared__ float s_pn[KK];

    const int u = blockIdx.y;
    const int base = blockIdx.x * CHUNK;
    const int tid = threadIdx.x;

    for (int i = tid; i < SS*KK*12; i += NTHREADS) s_ops[i] = g_ops[u*SS*KK*12 + i];
    if (tid < KK) s_pn[tid] = g_pn[u*KK + tid];

    const float* imgU = img + (size_t)u*CC*HW;
    const float* gpU = g_gp + (size_t)u*KK*HW;
    for (int p = tid; p < CHUNK; p += NTHREADS) {
        const int pix = base + p;
        s_img[p]          = imgU[pix];
        s_img[CHUNK+p]    = imgU[HW + pix];
        s_img[2*CHUNK+p]  = imgU[2*HW + pix];
        #pragma unroll
        for (int k = 0; k < KK; k++) s_gp[k*CHUNK + p] = gpU[k*HW + pix];
    }
    __syncthreads();

    const int warp = tid >> 5, lane = tid & 31;
    if (warp >= SS) return;
    const int s = warp;
    const float* shU = shifted + ((size_t)u*SS + s)*CC*HW;

    float acc[36];
    #pragma unroll
    for (int j = 0; j < 36; j++) acc[j] = 0.f;

    for (int i = 0; i < CHUNK/32; i++) {
        const int p = lane + 32*i;
        const int pix = base + p;
        const float x0 = shU[pix];
        const float x1 = shU[HW + pix];
        const float x2 = shU[2*HW + pix];
        const float pb0 = s_img[p], pb1 = s_img[CHUNK+p], pb2 = s_img[2*CHUNK+p];
        #pragma unroll
        for (int k = 0; k < KK; k++) {
            const float* O = s_ops + (s*KK+k)*12;
            const float d0 = x0 - (O[0]*pb0 + O[1]*pb1 + O[2]*pb2  + O[3]);
            const float d1 = x1 - (O[4]*pb0 + O[5]*pb1 + O[6]*pb2  + O[7]);
            const float d2 = x2 - (O[8]*pb0 + O[9]*pb1 + O[10]*pb2 + O[11]);
            const float w = s_gp[k*CHUNK + p] * s_pn[k];
            acc[k*6+0] += w*d0*d0;
            acc[k*6+1] += w*d0*d1;
            acc[k*6+2] += w*d0*d2;
            acc[k*6+3] += w*d1*d1;
            acc[k*6+4] += w*d1*d2;
            acc[k*6+5] += w*d2*d2;
        }
    }
    float* part = g_partC + (size_t)(u*NCHUNK + blockIdx.x)*(SS*KK*6);
    #pragma unroll
    for (int j = 0; j < 36; j++) {
        float v = acc[j];
        #pragma unroll
        for (int off = 16; off > 0; off >>= 1) v += __shfl_down_sync(0xffffffffu, v, off);
        if (lane == 0) part[s*36 + j] = v;
    }
}

// ---------------- sigma reduce + 3x3 inverse + logdet ----------------
__global__ void sigma_inv_kernel()
{
    __shared__ float s_ld[SS*KK];
    const int u = blockIdx.x;
    const int t = threadIdx.x;     // t = s*KK + k, block of 48
    const int s = t / KK, k = t % KK;

    float sig[6];
    #pragma unroll
    for (int j = 0; j < 6; j++) {
        float v = 0.f;
        const float* p = g_partC + (size_t)u*NCHUNK*(SS*KK*6) + s*36 + k*6 + j;
        for (int c = 0; c < NCHUNK; c++) v += p[c*(SS*KK*6)];
        sig[j] = v;
    }
    sig[0] += EPSF; sig[3] += EPSF; sig[5] += EPSF;

    const float a = sig[0], b = sig[1], c2 = sig[2], d = sig[3], e = sig[4], f = sig[5];
    const float A  = d*f - e*e;
    const float Bc = c2*e - b*f;
    const float Cc = b*e - c2*d;
    const float det = a*A + b*Bc + c2*Cc;
    const float idet = 1.f / det;

    float* Si = g_siginv + ((size_t)u*SS*KK + t)*6;
    Si[0] = A*idet;
    Si[1] = Bc*idet;
    Si[2] = Cc*idet;
    Si[3] = (a*f - c2*c2)*idet;
    Si[4] = (b*c2 - a*e)*idet;
    Si[5] = (a*d - b*b)*idet;

    s_ld[t] = logf(det);
    __syncthreads();
    if (t < KK) {
        float v = 0.f;
        for (int s2 = 0; s2 < SS; s2++) v += s_ld[s2*KK + t];
        g_ldsum[u*KK + t] = v;
    }
}

// ---------------- launch ----------------
extern "C" void kernel_launch(void* const* d_in, const int* in_sizes, int n_in,
                              void* d_out, int out_size)
{
    const float* img = nullptr;
    const float* sh = nullptr;
    const float* pred = nullptr;
    for (int i = 0; i < n_in; i++) {
        if (in_sizes[i] == BB*CC*HW)        img  = (const float*)d_in[i];
        else if (in_sizes[i] == BB*SS*CC*HW) sh  = (const float*)d_in[i];
        else if (in_sizes[i] == BB*KK*HW)   pred = (const float*)d_in[i];
    }
    float* out = (float*)d_out;

    dim3 grid(NCHUNK, BB);

    accum_kernel<0><<<grid, NTHREADS>>>(img, sh, pred, out);
    reduceA_kernel<<<BB, NSLOT>>>();
    for (int t = 0; t < 3; t++) {
        ops_kernel<<<1, BB*KK>>>();
        sigacc_kernel<<<grid, NTHREADS>>>(img, sh);
        sigma_inv_kernel<<<BB, SS*KK>>>();
        if (t < 2) {
            accum_kernel<1><<<grid, NTHREADS>>>(img, sh, pred, out);
            reduceA_kernel<<<BB, NSLOT>>>();
        } else {
            accum_kernel<2><<<grid, NTHREADS>>>(img, sh, pred, out);
        }
    }
}

// round 2
// speedup vs baseline: 5.9925x; 5.9925x over previous
#include <cuda_runtime.h>
#include <math.h>

#define BB 16
#define SS 8
#define CC 3
#define KK 6
#define HW 16384
#define CHUNK 256
#define NCHUNK (HW/CHUNK)     // 64
#define NTHREADS 288          // 9 warps
#define EPSF 1.1920928955078125e-07f

// partial slots per chunk:
//   F:   s*72 + k*12 + a*4 + b          [0,576)
//   XX:  576 + (s*KK+k)*6 + j           [576,864)
//   Sec: 864 + k*10 + j                 [864,924)
//   gpsum: 924 + k                      [924,930)
#define NSLOT 930

__device__ float g_part[BB*NCHUNK*NSLOT];
__device__ float g_ops[BB*SS*KK*12];     // float4-aligned per u (576 floats)
__device__ float g_siginv[BB*SS*KK*8];   // padded stride 8
__device__ float g_ldsum[BB*KK];

// MODE 0: softmax(pred) -> gp, accumulate moments
// MODE 1: quad -> gen -> softmax(pred+gen) -> gp, accumulate moments
// MODE 2: quad -> gen -> write output
template<int MODE>
__global__ __launch_bounds__(NTHREADS, 3)
void accum_kernel(const float* __restrict__ img, const float* __restrict__ shifted,
                  const float* __restrict__ pred, float* __restrict__ out)
{
    __shared__ float4 s_sh[SS][CHUNK];      // 32 KB
    __shared__ float4 s_img[CHUNK];         // 4 KB
    __shared__ float  s_gp[KK][CHUNK];      // 6 KB
    __shared__ float4 s_ops4[SS*KK*3];      // 2.25 KB
    __shared__ float4 s_sinv4[SS*KK*2];     // 1.5 KB
    __shared__ float  s_ld[KK];

    const int u    = blockIdx.y;
    const int base = blockIdx.x * CHUNK;
    const int tid  = threadIdx.x;

    if (MODE >= 1) {
        const float4* go = (const float4*)(g_ops + u*SS*KK*12);
        for (int i = tid; i < SS*KK*3; i += NTHREADS) s_ops4[i] = go[i];
        const float4* gs = (const float4*)(g_siginv + u*SS*KK*8);
        for (int i = tid; i < SS*KK*2; i += NTHREADS) s_sinv4[i] = gs[i];
        if (tid < KK) s_ld[tid] = g_ldsum[u*KK + tid];
        __syncthreads();
    }

    const float* imgU  = img + (size_t)u*CC*HW;
    const float* shU   = shifted + (size_t)u*SS*CC*HW;
    const float* predU = pred + (size_t)u*KK*HW;

    // ---- phase 1: per-pixel quad / softmax / staging ----
    if (tid < CHUNK) {
        const int p = tid;
        const int pix = base + p;
        const float pb0 = imgU[pix];
        const float pb1 = imgU[HW + pix];
        const float pb2 = imgU[2*HW + pix];
        if (MODE < 2) s_img[p] = make_float4(pb0, pb1, pb2, 1.0f);

        float q[KK];
        #pragma unroll
        for (int k = 0; k < KK; k++) q[k] = 0.f;

        #pragma unroll
        for (int s = 0; s < SS; s++) {
            const float x0 = shU[(s*CC+0)*HW + pix];
            const float x1 = shU[(s*CC+1)*HW + pix];
            const float x2 = shU[(s*CC+2)*HW + pix];
            if (MODE < 2) s_sh[s][p] = make_float4(x0, x1, x2, 0.f);
            if (MODE >= 1) {
                #pragma unroll
                for (int k = 0; k < KK; k++) {
                    const int m = (s*KK + k);
                    const float4 o0 = s_ops4[m*3+0];
                    const float4 o1 = s_ops4[m*3+1];
                    const float4 o2 = s_ops4[m*3+2];
                    const float d0 = x0 - (o0.x*pb0 + o0.y*pb1 + o0.z*pb2 + o0.w);
                    const float d1 = x1 - (o1.x*pb0 + o1.y*pb1 + o1.z*pb2 + o1.w);
                    const float d2 = x2 - (o2.x*pb0 + o2.y*pb1 + o2.z*pb2 + o2.w);
                    const float4 si0 = s_sinv4[m*2+0]; // s00 s01 s02 s11
                    const float4 si1 = s_sinv4[m*2+1]; // s12 s22 - -
                    q[k] += si0.x*d0*d0 + si0.w*d1*d1 + si1.y*d2*d2
                          + 2.f*(si0.y*d0*d1 + si0.z*d0*d2 + si1.x*d1*d2);
                }
            }
        }

        if (MODE == 2) {
            #pragma unroll
            for (int k = 0; k < KK; k++)
                out[((size_t)u*KK + k)*HW + pix] = -0.5f*q[k] - 0.5f*s_ld[k];
        } else {
            float lg[KK];
            float mx = -1e30f;
            #pragma unroll
            for (int k = 0; k < KK; k++) {
                const float gen = (MODE >= 1) ? (-0.5f*q[k] - 0.5f*s_ld[k]) : 0.f;
                lg[k] = predU[k*HW + pix] + gen;
                mx = fmaxf(mx, lg[k]);
            }
            float sum = 0.f;
            #pragma unroll
            for (int k = 0; k < KK; k++) { lg[k] = expf(lg[k] - mx); sum += lg[k]; }
            const float inv = 1.f / sum;
            #pragma unroll
            for (int k = 0; k < KK; k++) s_gp[k][p] = lg[k]*inv + EPSF;
        }
    }
    if (MODE == 2) return;
    __syncthreads();

    // ---- phase 2: moment accumulation ----
    const int warp = tid >> 5, lane = tid & 31;
    float* part = g_part + (size_t)(u*NCHUNK + blockIdx.x)*NSLOT;

    if (warp < SS) {
        const int s = warp;
        #pragma unroll
        for (int k = 0; k < KK; k++) {
            float f0=0,f1=0,f2=0,f3=0,f4=0,f5=0,f6=0,f7=0,f8=0,f9=0,f10=0,f11=0;
            float xx0=0,xx1=0,xx2=0,xx3=0,xx4=0,xx5=0;
            #pragma unroll
            for (int i = 0; i < CHUNK/32; i++) {
                const int p = lane + 32*i;
                const float4 x  = s_sh[s][p];
                const float4 pb = s_img[p];
                const float wk  = s_gp[k][p];
                const float t0 = x.x*wk, t1 = x.y*wk, t2 = x.z*wk;
                f0 += t0*pb.x; f1 += t0*pb.y; f2  += t0*pb.z; f3  += t0;
                f4 += t1*pb.x; f5 += t1*pb.y; f6  += t1*pb.z; f7  += t1;
                f8 += t2*pb.x; f9 += t2*pb.y; f10 += t2*pb.z; f11 += t2;
                xx0 += t0*x.x; xx1 += t0*x.y; xx2 += t0*x.z;
                xx3 += t1*x.y; xx4 += t1*x.z; xx5 += t2*x.z;
            }
            float acc[18] = {f0,f1,f2,f3,f4,f5,f6,f7,f8,f9,f10,f11,xx0,xx1,xx2,xx3,xx4,xx5};
            #pragma unroll
            for (int j = 0; j < 18; j++) {
                float v = acc[j];
                #pragma unroll
                for (int off = 16; off > 0; off >>= 1) v += __shfl_down_sync(0xffffffffu, v, off);
                if (lane == 0) {
                    if (j < 12) part[s*72 + k*12 + j] = v;
                    else        part[576 + (s*KK+k)*6 + (j-12)] = v;
                }
            }
        }
    } else {
        // warp 8: sym4 second moments + gp sums
        #pragma unroll
        for (int k = 0; k < KK; k++) {
            float a0=0,a1=0,a2=0,a3=0,a4=0,a5=0,a6=0,a7=0,a8=0,a9=0,gs=0;
            #pragma unroll
            for (int i = 0; i < CHUNK/32; i++) {
                const int p = lane + 32*i;
                const float4 pb = s_img[p];
                const float wk  = s_gp[k][p];
                const float w0 = wk*pb.x, w1 = wk*pb.y, w2 = wk*pb.z;
                a0 += w0*pb.x; a1 += w0*pb.y; a2 += w0*pb.z; a3 += w0;
                a4 += w1*pb.y; a5 += w1*pb.z; a6 += w1;
                a7 += w2*pb.z; a8 += w2;
                a9 += wk; gs += wk;
            }
            float acc[11] = {a0,a1,a2,a3,a4,a5,a6,a7,a8,a9,gs};
            #pragma unroll
            for (int j = 0; j < 11; j++) {
                float v = acc[j];
                #pragma unroll
                for (int off = 16; off > 0; off >>= 1) v += __shfl_down_sync(0xffffffffu, v, off);
                if (lane == 0) {
                    if (j < 10) part[864 + k*10 + j] = v;
                    else        part[924 + k] = v;
                }
            }
        }
    }
}

// ---------------- fused per-u solve: reduce + ops + closed-form sigma + inverse ----------------
__global__ void solve_kernel()
{
    __shared__ float m[NSLOT];
    __shared__ float s_Inv[KK][16];
    __shared__ float s_norm[KK];
    __shared__ float s_pn[KK];
    __shared__ float s_ld48[SS*KK];

    const int u = blockIdx.x;
    const int t = threadIdx.x;

    if (t < NSLOT) {
        const float* p = g_part + (size_t)u*NCHUNK*NSLOT + t;
        float v = 0.f;
        #pragma unroll 8
        for (int c = 0; c < NCHUNK; c++) v += p[(size_t)c*NSLOT];
        m[t] = v;
    }
    __syncthreads();

    if (t < KK) {
        const int k = t;
        const float* sec = m + 864 + k*10;
        const float trace = sec[0] + sec[4] + sec[7] + sec[9];
        const float norm = 1.f / trace;
        s_norm[k] = norm;
        s_pn[k] = 1.f / m[924 + k];

        float M[4][4], Inv[4][4];
        M[0][0]=sec[0]; M[0][1]=sec[1]; M[0][2]=sec[2]; M[0][3]=sec[3];
        M[1][0]=sec[1]; M[1][1]=sec[4]; M[1][2]=sec[5]; M[1][3]=sec[6];
        M[2][0]=sec[2]; M[2][1]=sec[5]; M[2][2]=sec[7]; M[2][3]=sec[8];
        M[3][0]=sec[3]; M[3][1]=sec[6]; M[3][2]=sec[8]; M[3][3]=sec[9];
        for (int i = 0; i < 4; i++) {
            for (int j = 0; j < 4; j++) { M[i][j] *= norm; Inv[i][j] = (i==j)?1.f:0.f; }
            M[i][i] += EPSF;
        }
        for (int col = 0; col < 4; col++) {
            int piv = col; float best = fabsf(M[col][col]);
            for (int r = col+1; r < 4; r++) {
                const float v = fabsf(M[r][col]);
                if (v > best) { best = v; piv = r; }
            }
            if (piv != col) {
                for (int j = 0; j < 4; j++) {
                    float tmp=M[col][j]; M[col][j]=M[piv][j]; M[piv][j]=tmp;
                    tmp=Inv[col][j]; Inv[col][j]=Inv[piv][j]; Inv[piv][j]=tmp;
                }
            }
            const float d = 1.f / M[col][col];
            for (int j = 0; j < 4; j++) { M[col][j] *= d; Inv[col][j] *= d; }
            for (int r = 0; r < 4; r++) {
                if (r == col) continue;
                const float f = M[r][col];
                for (int j = 0; j < 4; j++) { M[r][j] -= f*M[col][j]; Inv[r][j] -= f*Inv[col][j]; }
            }
        }
        for (int i = 0; i < 16; i++) s_Inv[k][i] = Inv[i/4][i%4];
    }
    __syncthreads();

    if (t < SS*KK) {
        const int s = t / KK, k = t % KK;
        const float norm = s_norm[k];
        const float pn   = s_pn[k];
        const float* F = m + s*72 + k*12;       // [3][4] raw
        const float* Sec10 = m + 864 + k*10;
        const float* XX = m + 576 + t*6;

        float Sec[4][4];
        Sec[0][0]=Sec10[0]; Sec[0][1]=Sec10[1]; Sec[0][2]=Sec10[2]; Sec[0][3]=Sec10[3];
        Sec[1][0]=Sec10[1]; Sec[1][1]=Sec10[4]; Sec[1][2]=Sec10[5]; Sec[1][3]=Sec10[6];
        Sec[2][0]=Sec10[2]; Sec[2][1]=Sec10[5]; Sec[2][2]=Sec10[7]; Sec[2][3]=Sec10[8];
        Sec[3][0]=Sec10[3]; Sec[3][1]=Sec10[6]; Sec[3][2]=Sec10[8]; Sec[3][3]=Sec10[9];

        float O[3][4];
        for (int a = 0; a < 3; a++)
            for (int b = 0; b < 4; b++) {
                float v = 0.f;
                for (int c = 0; c < 4; c++) v += (F[a*4+c]*norm) * s_Inv[k][c*4+b];
                O[a][b] = v;
            }
        float* go = g_ops + u*SS*KK*12 + t*12;
        for (int i = 0; i < 12; i++) go[i] = O[i/4][i%4];

        // sigma = pn*(XX - F O^T - (F O^T)^T + O Sec O^T) + EPS I
        float H[3][3];
        for (int a = 0; a < 3; a++)
            for (int b = 0; b < 3; b++) {
                float v = 0.f;
                for (int c = 0; c < 4; c++) v += F[a*4+c]*O[b][c];
                H[a][b] = v;
            }
        float G[3][4];
        for (int a = 0; a < 3; a++)
            for (int c = 0; c < 4; c++) {
                float v = 0.f;
                for (int cc = 0; cc < 4; cc++) v += O[a][cc]*Sec[cc][c];
                G[a][c] = v;
            }
        float GO[3][3];
        for (int a = 0; a < 3; a++)
            for (int b = a; b < 3; b++) {
                float v = 0.f;
                for (int c = 0; c < 4; c++) v += G[a][c]*O[b][c];
                GO[a][b] = v;
            }
        const float sa  = pn*(XX[0] - 2.f*H[0][0]          + GO[0][0]) + EPSF;
        const float sb  = pn*(XX[1] - H[0][1] - H[1][0]    + GO[0][1]);
        const float sc  = pn*(XX[2] - H[0][2] - H[2][0]    + GO[0][2]);
        const float sd  = pn*(XX[3] - 2.f*H[1][1]          + GO[1][1]) + EPSF;
        const float se  = pn*(XX[4] - H[1][2] - H[2][1]    + GO[1][2]);
        const float sf  = pn*(XX[5] - 2.f*H[2][2]          + GO[2][2]) + EPSF;

        const float A  = sd*sf - se*se;
        const float Bc = sc*se - sb*sf;
        const float Cc = sb*se - sc*sd;
        const float det = sa*A + sb*Bc + sc*Cc;
        const float idet = 1.f / det;

        float* Si = g_siginv + ((size_t)u*SS*KK + t)*8;
        Si[0] = A*idet;
        Si[1] = Bc*idet;
        Si[2] = Cc*idet;
        Si[3] = (sa*sf - sc*sc)*idet;
        Si[4] = (sb*sc - sa*se)*idet;
        Si[5] = (sa*sd - sb*sb)*idet;
        Si[6] = 0.f; Si[7] = 0.f;

        s_ld48[t] = logf(det);
    }
    __syncthreads();
    if (t < KK) {
        float v = 0.f;
        for (int s = 0; s < SS; s++) v += s_ld48[s*KK + t];
        g_ldsum[u*KK + t] = v;
    }
}

extern "C" void kernel_launch(void* const* d_in, const int* in_sizes, int n_in,
                              void* d_out, int out_size)
{
    const float* img = nullptr;
    const float* sh = nullptr;
    const float* pred = nullptr;
    for (int i = 0; i < n_in; i++) {
        if (in_sizes[i] == BB*CC*HW)         img  = (const float*)d_in[i];
        else if (in_sizes[i] == BB*SS*CC*HW) sh   = (const float*)d_in[i];
        else if (in_sizes[i] == BB*KK*HW)    pred = (const float*)d_in[i];
    }
    float* out = (float*)d_out;

    dim3 grid(NCHUNK, BB);

    accum_kernel<0><<<grid, NTHREADS>>>(img, sh, pred, out);
    solve_kernel<<<BB, 960>>>();
    accum_kernel<1><<<grid, NTHREADS>>>(img, sh, pred, out);
    solve_kernel<<<BB, 960>>>();
    accum_kernel<1><<<grid, NTHREADS>>>(img, sh, pred, out);
    solve_kernel<<<BB, 960>>>();
    accum_kernel<2><<<grid, NTHREADS>>>(img, sh, pred, out);
}